// round 6
// baseline (speedup 1.0000x reference)
#include <cuda_runtime.h>

// Problem constants (fixed shapes per reference)
#define NUM_EDGES 1000000
#define NUM_USERS 50000
#define NUM_ITEMS 20000
#define NRATE 5
#define NFEAT 64
#define KDIM (NRATE * NFEAT)   // 320

constexpr int NSEG_U = NUM_USERS * NRATE;   // 250,000
constexpr int NSEG_V = NUM_ITEMS * NRATE;   // 100,000
constexpr int NSEG   = NSEG_U + NSEG_V;     // 350,000

// Bucket capacities. Counts are Binomial(1M, 1/250K)~Poisson(4) (u-side) and
// Poisson(10) (v-side); P(count > cap) is ~1e-19 level. Writes are clamped to
// cap anyway so overflow cannot corrupt memory.
constexpr int CAP_U = 96;
constexpr int CAP_V = 160;

// ---------------------------------------------------------------------------
// Static device scratch (allocation is forbidden)
//   g_scratch: mean_u [50000][5][64] then mean_v [20000][5][64]  (fp32 MEANS)
//   g_cur:     per-(dst,rating) cursors == edge counts after fill
//   g_slots_*: bucket arrays holding the SOURCE node id per edge
// ---------------------------------------------------------------------------
constexpr size_t MEAN_U_OFF = 0;
constexpr size_t MEAN_V_OFF = (size_t)NSEG_U * NFEAT;                 // 16,000,000
constexpr size_t SCRATCH_TOTAL = MEAN_V_OFF + (size_t)NSEG_V * NFEAT; // 22,400,000 floats

__device__ __align__(16) float g_scratch[SCRATCH_TOTAL];
__device__ __align__(16) int   g_cur[NSEG];
__device__ int g_slots_u[(size_t)NSEG_U * CAP_U];   // 24M ints
__device__ int g_slots_v[(size_t)NSEG_V * CAP_V];   // 16M ints

// ---------------------------------------------------------------------------
// PTX helpers (packed f32x2 FMA for the transform GEMM)
// ---------------------------------------------------------------------------
__device__ __forceinline__ unsigned long long pack2(float x, float y) {
    unsigned long long d;
    asm("mov.b64 %0, {%1, %2};" : "=l"(d)
        : "r"(__float_as_uint(x)), "r"(__float_as_uint(y)));
    return d;
}
__device__ __forceinline__ void fma2(unsigned long long& d, unsigned long long a, unsigned long long b) {
    asm("fma.rn.f32x2 %0, %1, %2, %3;" : "=l"(d) : "l"(a), "l"(b), "l"(d));
}
__device__ __forceinline__ void unpack2(unsigned long long d, float& x, float& y) {
    unsigned int lo, hi;
    asm("mov.b64 {%0, %1}, %2;" : "=r"(lo), "=r"(hi) : "l"(d));
    x = __uint_as_float(lo);
    y = __uint_as_float(hi);
}

// ---------------------------------------------------------------------------
// Kernel 1: zero the cursors (1.4MB — replaces the old 91MB sum-zero)
// ---------------------------------------------------------------------------
__global__ void __launch_bounds__(256) zero_cur_kernel() {
    int i = blockIdx.x * blockDim.x + threadIdx.x;
    if (i < NSEG / 4) reinterpret_cast<int4*>(g_cur)[i] = make_int4(0, 0, 0, 0);
}

// ---------------------------------------------------------------------------
// Kernel 2: bucket fill. One thread per edge; cursor atomicAdd doubles as the
// histogram. Stores the SOURCE node id into the (dst,rating) bucket.
// ---------------------------------------------------------------------------
__global__ void __launch_bounds__(256) fill_kernel(
    const int* __restrict__ u_s,
    const int* __restrict__ v_s,
    const int* __restrict__ rate,
    int E)
{
    int e = blockIdx.x * blockDim.x + threadIdx.x;
    if (e >= E) return;

    int u = __ldg(u_s + e);
    int v = __ldg(v_s + e);
    int r = __ldg(rate + e);

    int segu = u * NRATE + r;
    int pos  = atomicAdd(g_cur + segu, 1);
    if (pos < CAP_U) g_slots_u[(size_t)segu * CAP_U + pos] = v;

    int segv = v * NRATE + r;
    int pos2 = atomicAdd(g_cur + NSEG_U + segv, 1);
    if (pos2 < CAP_V) g_slots_v[(size_t)segv * CAP_V + pos2] = u;
}

// ---------------------------------------------------------------------------
// Kernel 3: segmented mean. One warp per (dst,rating) segment.
//   - lanes cooperatively read the slot list (coalesced, one LDG for cnt<=32)
//   - per edge: warp gathers the 256B source row (lane -> float2), accumulates
//     in registers
//   - writes mean row (64 floats) — zeros for empty segments.
// No atomics, no RMW, no giant zero pass.
// ---------------------------------------------------------------------------
__global__ void __launch_bounds__(256) segment_mean_kernel(
    const float* __restrict__ x_user,
    const float* __restrict__ x_item)
{
    int gw   = (blockIdx.x * blockDim.x + threadIdx.x) >> 5;
    int lane = threadIdx.x & 31;
    if (gw >= NSEG) return;

    const float* __restrict__ x;
    const int*   __restrict__ slots;
    float* mean;
    int cap;
    if (gw < NSEG_U) {
        x     = x_item;                      // u-side aggregates ITEM features
        slots = g_slots_u + (size_t)gw * CAP_U;
        mean  = g_scratch + MEAN_U_OFF + (size_t)gw * NFEAT;
        cap   = CAP_U;
    } else {
        int s = gw - NSEG_U;
        x     = x_user;                      // v-side aggregates USER features
        slots = g_slots_v + (size_t)s * CAP_V;
        mean  = g_scratch + MEAN_V_OFF + (size_t)s * NFEAT;
        cap   = CAP_V;
    }

    int cnt = __ldg(g_cur + gw);             // broadcast load
    int cc  = min(cnt, cap);

    // Preload up to 32 slot ids with one coalesced read
    int my = (lane < cc) ? __ldg(slots + lane) : 0;

    float ax = 0.f, ay = 0.f;
    int i = 0;
    #pragma unroll 4
    for (; i < cc && i < 32; ++i) {
        int src = __shfl_sync(0xffffffffu, my, i);
        float2 f = *reinterpret_cast<const float2*>(x + (size_t)src * NFEAT + lane * 2);
        ax += f.x; ay += f.y;
    }
    for (; i < cc; ++i) {                    // astronomically rare tail
        int src = __ldg(slots + i);
        float2 f = *reinterpret_cast<const float2*>(x + (size_t)src * NFEAT + lane * 2);
        ax += f.x; ay += f.y;
    }

    float inv = 1.0f / (float)max(cnt, 1);
    float2 o; o.x = ax * inv; o.y = ay * inv;
    *reinterpret_cast<float2*>(mean + lane * 2) = o;
}

// ---------------------------------------------------------------------------
// Kernel 4: fused transform GEMM for both node sets.
//   out[n,h] = sum_k mean[n,k] * W[k,h]   (means already divided)
// 1095 blocks, 256 threads, 64x64 tile, K chunked by 32. Thread (c=t&15,
// g=t>>4) owns 4 nodes x 4 h; inner loop per k: 2x LDS.128 + 8 fma.rn.f32x2.
// ---------------------------------------------------------------------------
constexpr int UBLOCKS = (NUM_USERS + 63) / 64;   // 782
constexpr int VBLOCKS = (NUM_ITEMS + 63) / 64;   // 313

__global__ void __launch_bounds__(256) transform_fused_kernel(
    const float* __restrict__ W,
    float*       __restrict__ out)
{
    __shared__ float As[32][64];   // [k][node]
    __shared__ float Bs[32][64];   // [k][h]

    int b = blockIdx.x;
    const float* means;
    int n_nodes, nodeBase;
    float* o;
    if (b < UBLOCKS) {
        means = g_scratch + MEAN_U_OFF;
        n_nodes = NUM_USERS; nodeBase = b * 64; o = out;
    } else {
        means = g_scratch + MEAN_V_OFF;
        n_nodes = NUM_ITEMS; nodeBase = (b - UBLOCKS) * 64;
        o = out + (size_t)NUM_USERS * NFEAT;
    }

    int t = threadIdx.x;
    int c = t & 15;          // h group: h = 4c..4c+3
    int g = t >> 4;          // node group: nodes g*4..g*4+3

    // A-staging: node nLoc, 8 consecutive k's starting at ks
    int nLoc = t & 63;
    int ks   = (t >> 6) * 8;

    unsigned long long acc01[4], acc23[4];
    #pragma unroll
    for (int i = 0; i < 4; ++i) { acc01[i] = 0ull; acc23[i] = 0ull; }

    for (int kc = 0; kc < KDIM / 32; ++kc) {
        int k0 = kc * 32;

        // ---- stage A: copy mean chunk ----
        {
            int n = nodeBase + nLoc;
            bool valid = (n < n_nodes);
            const float* src = means + (size_t)n * KDIM + k0 + ks;
            float4 s0 = valid ? *reinterpret_cast<const float4*>(src)
                              : make_float4(0.f, 0.f, 0.f, 0.f);
            float4 s1 = valid ? *reinterpret_cast<const float4*>(src + 4)
                              : make_float4(0.f, 0.f, 0.f, 0.f);
            As[ks + 0][nLoc] = s0.x;  As[ks + 1][nLoc] = s0.y;
            As[ks + 2][nLoc] = s0.z;  As[ks + 3][nLoc] = s0.w;
            As[ks + 4][nLoc] = s1.x;  As[ks + 5][nLoc] = s1.y;
            As[ks + 6][nLoc] = s1.z;  As[ks + 7][nLoc] = s1.w;
        }
        // ---- stage B: weight chunk [32][64] ----
        {
            const float4* wsrc = reinterpret_cast<const float4*>(W + (size_t)k0 * 64);
            float4* bdst = reinterpret_cast<float4*>(&Bs[0][0]);
            bdst[t]       = wsrc[t];
            bdst[t + 256] = wsrc[t + 256];
        }
        __syncthreads();

        // ---- compute: 32 k-steps ----
        #pragma unroll
        for (int k = 0; k < 32; ++k) {
            float4 a4 = *reinterpret_cast<const float4*>(&As[k][g * 4]);
            float4 b4 = *reinterpret_cast<const float4*>(&Bs[k][c * 4]);
            unsigned long long bxy = pack2(b4.x, b4.y);
            unsigned long long bzw = pack2(b4.z, b4.w);
            unsigned long long a0 = pack2(a4.x, a4.x);
            unsigned long long a1 = pack2(a4.y, a4.y);
            unsigned long long a2 = pack2(a4.z, a4.z);
            unsigned long long a3 = pack2(a4.w, a4.w);
            fma2(acc01[0], a0, bxy); fma2(acc23[0], a0, bzw);
            fma2(acc01[1], a1, bxy); fma2(acc23[1], a1, bzw);
            fma2(acc01[2], a2, bxy); fma2(acc23[2], a2, bzw);
            fma2(acc01[3], a3, bxy); fma2(acc23[3], a3, bzw);
        }
        __syncthreads();
    }

    #pragma unroll
    for (int i = 0; i < 4; ++i) {
        int n = nodeBase + g * 4 + i;
        if (n < n_nodes) {
            float4 ov;
            unpack2(acc01[i], ov.x, ov.y);
            unpack2(acc23[i], ov.z, ov.w);
            *reinterpret_cast<float4*>(o + (size_t)n * NFEAT + c * 4) = ov;
        }
    }
}

// ---------------------------------------------------------------------------
// Launch
// ---------------------------------------------------------------------------
extern "C" void kernel_launch(void* const* d_in, const int* in_sizes, int n_in,
                              void* d_out, int out_size)
{
    const int*   u_s    = (const int*)  d_in[0];
    const int*   v_s    = (const int*)  d_in[1];
    const int*   rate   = (const int*)  d_in[2];
    const float* x_user = (const float*)d_in[3];
    const float* x_item = (const float*)d_in[4];
    const float* weight = (const float*)d_in[5];
    float* out = (float*)d_out;

    int E = in_sizes[0];

    zero_cur_kernel<<<(NSEG / 4 + 255) / 256, 256>>>();

    fill_kernel<<<(E + 255) / 256, 256>>>(u_s, v_s, rate, E);

    // one warp per segment, 8 warps per block
    segment_mean_kernel<<<(NSEG + 7) / 8, 256>>>(x_user, x_item);

    transform_fused_kernel<<<UBLOCKS + VBLOCKS, 256>>>(weight, out);
}

// round 7
// speedup vs baseline: 1.1018x; 1.1018x over previous
#include <cuda_runtime.h>

// Problem constants (fixed shapes per reference)
#define NUM_EDGES 1000000
#define NUM_USERS 50000
#define NUM_ITEMS 20000
#define NRATE 5
#define NFEAT 64
#define KDIM (NRATE * NFEAT)   // 320

constexpr int NSEG_U = NUM_USERS * NRATE;   // 250,000
constexpr int NSEG_V = NUM_ITEMS * NRATE;   // 100,000
constexpr int NSEG   = NSEG_U + NSEG_V;     // 350,000

// Bucket capacities. Counts are ~Poisson(4) (u-side) / ~Poisson(10) (v-side).
// P(overflow anywhere) ~ 1e-9; writes clamp to cap so overflow cannot corrupt.
// CAP_U=32 makes each u slot-row exactly one 128B line; total slots 57.6MB
// stays L2-resident between fill and segment.
constexpr int CAP_U = 32;
constexpr int CAP_V = 64;

// ---------------------------------------------------------------------------
// Static device scratch (allocation is forbidden)
//   g_scratch: mean_u [50000][5][64] then mean_v [20000][5][64]  (fp32 MEANS)
//   g_cur:     per-(dst,rating) cursors == edge counts after fill
//   g_slots_*: bucket arrays holding the SOURCE node id per edge
// ---------------------------------------------------------------------------
constexpr size_t MEAN_U_OFF = 0;
constexpr size_t MEAN_V_OFF = (size_t)NSEG_U * NFEAT;                 // 16,000,000
constexpr size_t SCRATCH_TOTAL = MEAN_V_OFF + (size_t)NSEG_V * NFEAT; // 22,400,000 floats

__device__ __align__(16) float g_scratch[SCRATCH_TOTAL];
__device__ __align__(16) int   g_cur[NSEG];
__device__ __align__(16) int   g_slots_u[(size_t)NSEG_U * CAP_U];   // 32MB
__device__ __align__(16) int   g_slots_v[(size_t)NSEG_V * CAP_V];   // 25.6MB

// ---------------------------------------------------------------------------
// PTX helpers (packed f32x2 FMA for the transform GEMM)
// ---------------------------------------------------------------------------
__device__ __forceinline__ unsigned long long pack2(float x, float y) {
    unsigned long long d;
    asm("mov.b64 %0, {%1, %2};" : "=l"(d)
        : "r"(__float_as_uint(x)), "r"(__float_as_uint(y)));
    return d;
}
__device__ __forceinline__ void fma2(unsigned long long& d, unsigned long long a, unsigned long long b) {
    asm("fma.rn.f32x2 %0, %1, %2, %3;" : "=l"(d) : "l"(a), "l"(b), "l"(d));
}
__device__ __forceinline__ void unpack2(unsigned long long d, float& x, float& y) {
    unsigned int lo, hi;
    asm("mov.b64 {%0, %1}, %2;" : "=r"(lo), "=r"(hi) : "l"(d));
    x = __uint_as_float(lo);
    y = __uint_as_float(hi);
}

// ---------------------------------------------------------------------------
// Kernel 1: zero the cursors (1.4MB)
// ---------------------------------------------------------------------------
__global__ void __launch_bounds__(256) zero_cur_kernel() {
    int i = blockIdx.x * blockDim.x + threadIdx.x;
    if (i < NSEG / 4) reinterpret_cast<int4*>(g_cur)[i] = make_int4(0, 0, 0, 0);
}

// ---------------------------------------------------------------------------
// Kernel 2: bucket fill. One thread per edge; cursor atomicAdd doubles as the
// histogram. Stores the SOURCE node id into the (dst,rating) bucket.
// ---------------------------------------------------------------------------
__global__ void __launch_bounds__(256) fill_kernel(
    const int* __restrict__ u_s,
    const int* __restrict__ v_s,
    const int* __restrict__ rate,
    int E)
{
    int e = blockIdx.x * blockDim.x + threadIdx.x;
    if (e >= E) return;

    int u = __ldg(u_s + e);
    int v = __ldg(v_s + e);
    int r = __ldg(rate + e);

    int segu = u * NRATE + r;
    int pos  = atomicAdd(g_cur + segu, 1);
    if (pos < CAP_U) g_slots_u[(size_t)segu * CAP_U + pos] = v;

    int segv = v * NRATE + r;
    int pos2 = atomicAdd(g_cur + NSEG_U + segv, 1);
    if (pos2 < CAP_V) g_slots_v[(size_t)segv * CAP_V + pos2] = u;
}

// ---------------------------------------------------------------------------
// Kernel 3: segmented mean. One warp per (dst,rating) segment.
// Lanes preload the slot list (coalesced), shuffle-broadcast each source id,
// gather the 256B feature row (lane -> float2), accumulate in registers,
// write the mean row once. No atomics, no RMW.
// ---------------------------------------------------------------------------
__global__ void __launch_bounds__(256) segment_mean_kernel(
    const float* __restrict__ x_user,
    const float* __restrict__ x_item)
{
    int gw   = (blockIdx.x * blockDim.x + threadIdx.x) >> 5;
    int lane = threadIdx.x & 31;
    if (gw >= NSEG) return;

    const float* __restrict__ x;
    const int*   __restrict__ slots;
    float* mean;
    int cap;
    if (gw < NSEG_U) {
        x     = x_item;                      // u-side aggregates ITEM features
        slots = g_slots_u + (size_t)gw * CAP_U;
        mean  = g_scratch + MEAN_U_OFF + (size_t)gw * NFEAT;
        cap   = CAP_U;
    } else {
        int s = gw - NSEG_U;
        x     = x_user;                      // v-side aggregates USER features
        slots = g_slots_v + (size_t)s * CAP_V;
        mean  = g_scratch + MEAN_V_OFF + (size_t)s * NFEAT;
        cap   = CAP_V;
    }

    int cnt = __ldg(g_cur + gw);
    int cc  = min(cnt, cap);

    int my = (lane < cc) ? __ldg(slots + lane) : 0;

    float ax = 0.f, ay = 0.f;
    int i = 0;
    #pragma unroll 4
    for (; i < cc && i < 32; ++i) {
        int src = __shfl_sync(0xffffffffu, my, i);
        float2 f = *reinterpret_cast<const float2*>(x + (size_t)src * NFEAT + lane * 2);
        ax += f.x; ay += f.y;
    }
    for (; i < cc; ++i) {                    // rare tail (v-side cnt>32)
        int src = __ldg(slots + i);
        float2 f = *reinterpret_cast<const float2*>(x + (size_t)src * NFEAT + lane * 2);
        ax += f.x; ay += f.y;
    }

    float inv = 1.0f / (float)max(cnt, 1);
    float2 o; o.x = ax * inv; o.y = ay * inv;
    *reinterpret_cast<float2*>(mean + lane * 2) = o;
}

// ---------------------------------------------------------------------------
// Kernel 4: fused transform GEMM, 8x8 register tile.
//   out[n,h] = sum_k mean[n,k] * W[k,h]
// Tile = 256 nodes x 64 h, 256 threads, K chunked by 16.
// Thread (tx = t&7, ty = t>>3) owns nodes {ty*4..+3, 128+ty*4..+3} and
// h {tx*4..+3, 32+tx*4..+3}. Per k: 4 conflict-free LDS.128 (64B) feed
// 32 packed fma.rn.f32x2 -> 2 MACs per LDS byte (4x the R6 intensity).
// ---------------------------------------------------------------------------
constexpr int TILE_N  = 256;
constexpr int UBLOCKS = (NUM_USERS + TILE_N - 1) / TILE_N;   // 196
constexpr int VBLOCKS = (NUM_ITEMS + TILE_N - 1) / TILE_N;   // 79
constexpr int KCHUNK  = 16;

__global__ void __launch_bounds__(256) transform_fused_kernel(
    const float* __restrict__ W,
    float*       __restrict__ out)
{
    __shared__ float As[KCHUNK][TILE_N];   // 16KB [k][node]
    __shared__ float Bs[KCHUNK][64];       // 4KB  [k][h]

    int b = blockIdx.x;
    const float* means;
    int n_nodes, nodeBase;
    float* o;
    if (b < UBLOCKS) {
        means = g_scratch + MEAN_U_OFF;
        n_nodes = NUM_USERS; nodeBase = b * TILE_N; o = out;
    } else {
        means = g_scratch + MEAN_V_OFF;
        n_nodes = NUM_ITEMS; nodeBase = (b - UBLOCKS) * TILE_N;
        o = out + (size_t)NUM_USERS * NFEAT;
    }

    int t  = threadIdx.x;
    int tx = t & 7;          // h groups: tx*4 and 32+tx*4
    int ty = t >> 3;         // node groups: ty*4 and 128+ty*4

    // A-staging role: thread t stages node (nodeBase + t), 16 k's per chunk
    int nStage = nodeBase + t;
    bool sValid = (nStage < n_nodes);
    const float* srowBase = means + (size_t)nStage * KDIM;

    unsigned long long acc[8][4];
    #pragma unroll
    for (int i = 0; i < 8; ++i)
        #pragma unroll
        for (int j = 0; j < 4; ++j) acc[i][j] = 0ull;

    for (int kc = 0; kc < KDIM / KCHUNK; ++kc) {
        int k0 = kc * KCHUNK;

        // ---- stage A: 256 threads x 16 k (4 float4 loads, transposed STS) ----
        {
            const float* src = srowBase + k0;
            #pragma unroll
            for (int j = 0; j < 4; ++j) {
                float4 s = sValid ? *reinterpret_cast<const float4*>(src + j * 4)
                                  : make_float4(0.f, 0.f, 0.f, 0.f);
                As[j * 4 + 0][t] = s.x;
                As[j * 4 + 1][t] = s.y;
                As[j * 4 + 2][t] = s.z;
                As[j * 4 + 3][t] = s.w;
            }
        }
        // ---- stage B: weight chunk [16][64] = 256 float4, one per thread ----
        {
            reinterpret_cast<float4*>(&Bs[0][0])[t] =
                reinterpret_cast<const float4*>(W + (size_t)k0 * 64)[t];
        }
        __syncthreads();

        // ---- compute: 16 k-steps, 32 FMA2 each ----
        #pragma unroll
        for (int k = 0; k < KCHUNK; ++k) {
            float4 a0 = *reinterpret_cast<const float4*>(&As[k][ty * 4]);
            float4 a1 = *reinterpret_cast<const float4*>(&As[k][ty * 4 + 128]);
            float4 b0 = *reinterpret_cast<const float4*>(&Bs[k][tx * 4]);
            float4 b1 = *reinterpret_cast<const float4*>(&Bs[k][tx * 4 + 32]);
            unsigned long long b0xy = pack2(b0.x, b0.y);
            unsigned long long b0zw = pack2(b0.z, b0.w);
            unsigned long long b1xy = pack2(b1.x, b1.y);
            unsigned long long b1zw = pack2(b1.z, b1.w);
            float av[8] = {a0.x, a0.y, a0.z, a0.w, a1.x, a1.y, a1.z, a1.w};
            #pragma unroll
            for (int i = 0; i < 8; ++i) {
                unsigned long long aa = pack2(av[i], av[i]);
                fma2(acc[i][0], aa, b0xy);
                fma2(acc[i][1], aa, b0zw);
                fma2(acc[i][2], aa, b1xy);
                fma2(acc[i][3], aa, b1zw);
            }
        }
        __syncthreads();
    }

    // ---- epilogue: 8 nodes x (2 float4 stores) ----
    #pragma unroll
    for (int i = 0; i < 8; ++i) {
        int nLoc = (i < 4) ? (ty * 4 + i) : (128 + ty * 4 + (i - 4));
        int n = nodeBase + nLoc;
        if (n < n_nodes) {
            float4 o0, o1;
            unpack2(acc[i][0], o0.x, o0.y);
            unpack2(acc[i][1], o0.z, o0.w);
            unpack2(acc[i][2], o1.x, o1.y);
            unpack2(acc[i][3], o1.z, o1.w);
            float* orow = o + (size_t)n * NFEAT;
            *reinterpret_cast<float4*>(orow + tx * 4)      = o0;
            *reinterpret_cast<float4*>(orow + tx * 4 + 32) = o1;
        }
    }
}

// ---------------------------------------------------------------------------
// Launch
// ---------------------------------------------------------------------------
extern "C" void kernel_launch(void* const* d_in, const int* in_sizes, int n_in,
                              void* d_out, int out_size)
{
    const int*   u_s    = (const int*)  d_in[0];
    const int*   v_s    = (const int*)  d_in[1];
    const int*   rate   = (const int*)  d_in[2];
    const float* x_user = (const float*)d_in[3];
    const float* x_item = (const float*)d_in[4];
    const float* weight = (const float*)d_in[5];
    float* out = (float*)d_out;

    int E = in_sizes[0];

    zero_cur_kernel<<<(NSEG / 4 + 255) / 256, 256>>>();

    fill_kernel<<<(E + 255) / 256, 256>>>(u_s, v_s, rate, E);

    segment_mean_kernel<<<(NSEG + 7) / 8, 256>>>(x_user, x_item);

    transform_fused_kernel<<<UBLOCKS + VBLOCKS, 256>>>(weight, out);
}

// round 8
// speedup vs baseline: 1.1372x; 1.0322x over previous
#include <cuda_runtime.h>

// Problem constants (fixed shapes per reference)
#define NUM_EDGES 1000000
#define NUM_USERS 50000
#define NUM_ITEMS 20000
#define NRATE 5
#define NFEAT 64
#define KDIM (NRATE * NFEAT)   // 320

constexpr int NSEG_U = NUM_USERS * NRATE;   // 250,000
constexpr int NSEG_V = NUM_ITEMS * NRATE;   // 100,000
constexpr int NSEG   = NSEG_U + NSEG_V;     // 350,000

// Bucket capacities: counts ~Poisson(4) (u) / ~Poisson(10) (v); overflow
// probability ~1e-9 and writes clamp to cap so it can't corrupt memory.
constexpr int CAP_U = 32;
constexpr int CAP_V = 64;

// ---------------------------------------------------------------------------
// Static device scratch
// ---------------------------------------------------------------------------
constexpr size_t MEAN_U_OFF = 0;
constexpr size_t MEAN_V_OFF = (size_t)NSEG_U * NFEAT;                 // 16,000,000
constexpr size_t SCRATCH_TOTAL = MEAN_V_OFF + (size_t)NSEG_V * NFEAT; // 22,400,000 floats

__device__ __align__(16) float g_scratch[SCRATCH_TOTAL];
__device__ __align__(16) int   g_cur[NSEG];
__device__ __align__(16) int   g_slots_u[(size_t)NSEG_U * CAP_U];   // 32MB
__device__ __align__(16) int   g_slots_v[(size_t)NSEG_V * CAP_V];   // 25.6MB

// ---------------------------------------------------------------------------
// PTX helpers
// ---------------------------------------------------------------------------
__device__ __forceinline__ unsigned long long pack2(float x, float y) {
    unsigned long long d;
    asm("mov.b64 %0, {%1, %2};" : "=l"(d)
        : "r"(__float_as_uint(x)), "r"(__float_as_uint(y)));
    return d;
}
__device__ __forceinline__ void fma2(unsigned long long& d, unsigned long long a, unsigned long long b) {
    asm("fma.rn.f32x2 %0, %1, %2, %3;" : "=l"(d) : "l"(a), "l"(b), "l"(d));
}
__device__ __forceinline__ void unpack2(unsigned long long d, float& x, float& y) {
    unsigned int lo, hi;
    asm("mov.b64 {%0, %1}, %2;" : "=r"(lo), "=r"(hi) : "l"(d));
    x = __uint_as_float(lo);
    y = __uint_as_float(hi);
}

// ---------------------------------------------------------------------------
// Kernel 1: zero the cursors (1.4MB)
// ---------------------------------------------------------------------------
__global__ void __launch_bounds__(256) zero_cur_kernel() {
    int i = blockIdx.x * blockDim.x + threadIdx.x;
    if (i < NSEG / 4) reinterpret_cast<int4*>(g_cur)[i] = make_int4(0, 0, 0, 0);
}

// ---------------------------------------------------------------------------
// Kernel 2: bucket fill (cursor atomicAdd doubles as histogram)
// ---------------------------------------------------------------------------
__global__ void __launch_bounds__(256) fill_kernel(
    const int* __restrict__ u_s,
    const int* __restrict__ v_s,
    const int* __restrict__ rate,
    int E)
{
    int e = blockIdx.x * blockDim.x + threadIdx.x;
    if (e >= E) return;

    int u = __ldg(u_s + e);
    int v = __ldg(v_s + e);
    int r = __ldg(rate + e);

    int segu = u * NRATE + r;
    int pos  = atomicAdd(g_cur + segu, 1);
    if (pos < CAP_U) g_slots_u[(size_t)segu * CAP_U + pos] = v;

    int segv = v * NRATE + r;
    int pos2 = atomicAdd(g_cur + NSEG_U + segv, 1);
    if (pos2 < CAP_V) g_slots_v[(size_t)segv * CAP_V + pos2] = u;
}

// ---------------------------------------------------------------------------
// Kernel 3: segmented mean. One warp per (dst,rating) segment.
// TWO source rows per iteration: lanes 0-15 cover row 2p (float4 each =
// 256B coalesced), lanes 16-31 row 2p+1. Unroll 4 -> 8 rows of loads in
// flight per warp. shfl_xor(16) combines the two halves at the end.
// ---------------------------------------------------------------------------
__global__ void __launch_bounds__(256) segment_mean_kernel(
    const float* __restrict__ x_user,
    const float* __restrict__ x_item)
{
    int gw   = (blockIdx.x * blockDim.x + threadIdx.x) >> 5;
    int lane = threadIdx.x & 31;
    if (gw >= NSEG) return;

    const float* __restrict__ x;
    const int*   __restrict__ slots;
    float* mean;
    int cap;
    if (gw < NSEG_U) {
        x     = x_item;                      // u-side aggregates ITEM features
        slots = g_slots_u + (size_t)gw * CAP_U;
        mean  = g_scratch + MEAN_U_OFF + (size_t)gw * NFEAT;
        cap   = CAP_U;
    } else {
        int s = gw - NSEG_U;
        x     = x_user;                      // v-side aggregates USER features
        slots = g_slots_v + (size_t)s * CAP_V;
        mean  = g_scratch + MEAN_V_OFF + (size_t)s * NFEAT;
        cap   = CAP_V;
    }

    int cnt = __ldg(g_cur + gw);
    int cc  = min(cnt, cap);

    int half = lane >> 4;        // which of the 2 rows this lane works on
    int fl   = lane & 15;        // float4 position within the row

    // Preload up to 32 slot ids (one coalesced 128B read)
    int my = (lane < min(cc, 32)) ? __ldg(slots + lane) : 0;

    float4 acc = make_float4(0.f, 0.f, 0.f, 0.f);

    int cmain = min(cc, 32);
    int npair = (cmain + 1) >> 1;
    #pragma unroll 4
    for (int p = 0; p < npair; ++p) {
        int e = 2 * p + half;
        int src = __shfl_sync(0xffffffffu, my, e & 31);
        if (e < cmain) {
            float4 f = *reinterpret_cast<const float4*>(x + (size_t)src * NFEAT + fl * 4);
            acc.x += f.x; acc.y += f.y; acc.z += f.z; acc.w += f.w;
        }
    }
    // rare tail (cc > 32; essentially never at these Poisson rates)
    for (int e = 32 + half; e < cc; e += 2) {
        int src = __ldg(slots + e);
        float4 f = *reinterpret_cast<const float4*>(x + (size_t)src * NFEAT + fl * 4);
        acc.x += f.x; acc.y += f.y; acc.z += f.z; acc.w += f.w;
    }

    // combine the two half-warp partial sums (same features, different rows)
    acc.x += __shfl_xor_sync(0xffffffffu, acc.x, 16);
    acc.y += __shfl_xor_sync(0xffffffffu, acc.y, 16);
    acc.z += __shfl_xor_sync(0xffffffffu, acc.z, 16);
    acc.w += __shfl_xor_sync(0xffffffffu, acc.w, 16);

    if (lane < 16) {
        float inv = 1.0f / (float)max(cnt, 1);
        float4 o;
        o.x = acc.x * inv; o.y = acc.y * inv;
        o.z = acc.z * inv; o.w = acc.w * inv;
        *reinterpret_cast<float4*>(mean + fl * 4) = o;
    }
}

// ---------------------------------------------------------------------------
// Kernel 4: fused transform GEMM, 8x8 register tile, software-prefetched.
//   out[n,h] = sum_k mean[n,k] * W[k,h]
// Tile = 256 nodes x 64 h, 256 threads, K chunked by 16.
// Pipeline per chunk: STS(prefetched regs) -> sync -> issue LDGs for NEXT
// chunk -> compute 16 k -> sync.  The ~250cyc L2 latency of the chunk load
// hides under the compute of the previous chunk.
// ---------------------------------------------------------------------------
constexpr int TILE_N  = 256;
constexpr int UBLOCKS = (NUM_USERS + TILE_N - 1) / TILE_N;   // 196
constexpr int VBLOCKS = (NUM_ITEMS + TILE_N - 1) / TILE_N;   // 79
constexpr int KCHUNK  = 16;
constexpr int NCHUNKS = KDIM / KCHUNK;                       // 20

__global__ void __launch_bounds__(256) transform_fused_kernel(
    const float* __restrict__ W,
    float*       __restrict__ out)
{
    __shared__ float As[KCHUNK][TILE_N];   // 16KB [k][node]
    __shared__ float Bs[KCHUNK][64];       // 4KB  [k][h]

    int b = blockIdx.x;
    const float* means;
    int n_nodes, nodeBase;
    float* o;
    if (b < UBLOCKS) {
        means = g_scratch + MEAN_U_OFF;
        n_nodes = NUM_USERS; nodeBase = b * TILE_N; o = out;
    } else {
        means = g_scratch + MEAN_V_OFF;
        n_nodes = NUM_ITEMS; nodeBase = (b - UBLOCKS) * TILE_N;
        o = out + (size_t)NUM_USERS * NFEAT;
    }

    int t  = threadIdx.x;
    int tx = t & 7;          // h groups: tx*4 and 32+tx*4
    int ty = t >> 3;         // node groups: ty*4 and 128+ty*4

    int nStage = nodeBase + t;
    bool sValid = (nStage < n_nodes);
    const float* srowBase = means + (size_t)nStage * KDIM;

    unsigned long long acc[8][4];
    #pragma unroll
    for (int i = 0; i < 8; ++i)
        #pragma unroll
        for (int j = 0; j < 4; ++j) acc[i][j] = 0ull;

    // prologue: fetch chunk 0 into registers
    float4 sreg[4];
    float4 wreg;
    #pragma unroll
    for (int j = 0; j < 4; ++j)
        sreg[j] = sValid ? *reinterpret_cast<const float4*>(srowBase + j * 4)
                         : make_float4(0.f, 0.f, 0.f, 0.f);
    wreg = reinterpret_cast<const float4*>(W)[t];

    for (int kc = 0; kc < NCHUNKS; ++kc) {
        // ---- commit prefetched chunk to smem ----
        #pragma unroll
        for (int j = 0; j < 4; ++j) {
            As[j * 4 + 0][t] = sreg[j].x;
            As[j * 4 + 1][t] = sreg[j].y;
            As[j * 4 + 2][t] = sreg[j].z;
            As[j * 4 + 3][t] = sreg[j].w;
        }
        reinterpret_cast<float4*>(&Bs[0][0])[t] = wreg;
        __syncthreads();

        // ---- issue next chunk's LDGs (latency hides under compute) ----
        if (kc + 1 < NCHUNKS) {
            const float* src = srowBase + (kc + 1) * KCHUNK;
            #pragma unroll
            for (int j = 0; j < 4; ++j)
                sreg[j] = sValid ? *reinterpret_cast<const float4*>(src + j * 4)
                                 : make_float4(0.f, 0.f, 0.f, 0.f);
            wreg = reinterpret_cast<const float4*>(W + (size_t)(kc + 1) * KCHUNK * 64)[t];
        }

        // ---- compute 16 k-steps, 32 FMA2 each ----
        #pragma unroll
        for (int k = 0; k < KCHUNK; ++k) {
            float4 a0 = *reinterpret_cast<const float4*>(&As[k][ty * 4]);
            float4 a1 = *reinterpret_cast<const float4*>(&As[k][ty * 4 + 128]);
            float4 b0 = *reinterpret_cast<const float4*>(&Bs[k][tx * 4]);
            float4 b1 = *reinterpret_cast<const float4*>(&Bs[k][tx * 4 + 32]);
            unsigned long long b0xy = pack2(b0.x, b0.y);
            unsigned long long b0zw = pack2(b0.z, b0.w);
            unsigned long long b1xy = pack2(b1.x, b1.y);
            unsigned long long b1zw = pack2(b1.z, b1.w);
            unsigned long long aa;
            aa = pack2(a0.x, a0.x);
            fma2(acc[0][0], aa, b0xy); fma2(acc[0][1], aa, b0zw);
            fma2(acc[0][2], aa, b1xy); fma2(acc[0][3], aa, b1zw);
            aa = pack2(a0.y, a0.y);
            fma2(acc[1][0], aa, b0xy); fma2(acc[1][1], aa, b0zw);
            fma2(acc[1][2], aa, b1xy); fma2(acc[1][3], aa, b1zw);
            aa = pack2(a0.z, a0.z);
            fma2(acc[2][0], aa, b0xy); fma2(acc[2][1], aa, b0zw);
            fma2(acc[2][2], aa, b1xy); fma2(acc[2][3], aa, b1zw);
            aa = pack2(a0.w, a0.w);
            fma2(acc[3][0], aa, b0xy); fma2(acc[3][1], aa, b0zw);
            fma2(acc[3][2], aa, b1xy); fma2(acc[3][3], aa, b1zw);
            aa = pack2(a1.x, a1.x);
            fma2(acc[4][0], aa, b0xy); fma2(acc[4][1], aa, b0zw);
            fma2(acc[4][2], aa, b1xy); fma2(acc[4][3], aa, b1zw);
            aa = pack2(a1.y, a1.y);
            fma2(acc[5][0], aa, b0xy); fma2(acc[5][1], aa, b0zw);
            fma2(acc[5][2], aa, b1xy); fma2(acc[5][3], aa, b1zw);
            aa = pack2(a1.z, a1.z);
            fma2(acc[6][0], aa, b0xy); fma2(acc[6][1], aa, b0zw);
            fma2(acc[6][2], aa, b1xy); fma2(acc[6][3], aa, b1zw);
            aa = pack2(a1.w, a1.w);
            fma2(acc[7][0], aa, b0xy); fma2(acc[7][1], aa, b0zw);
            fma2(acc[7][2], aa, b1xy); fma2(acc[7][3], aa, b1zw);
        }
        __syncthreads();
    }

    // ---- epilogue ----
    #pragma unroll
    for (int i = 0; i < 8; ++i) {
        int nLoc = (i < 4) ? (ty * 4 + i) : (128 + ty * 4 + (i - 4));
        int n = nodeBase + nLoc;
        if (n < n_nodes) {
            float4 o0, o1;
            unpack2(acc[i][0], o0.x, o0.y);
            unpack2(acc[i][1], o0.z, o0.w);
            unpack2(acc[i][2], o1.x, o1.y);
            unpack2(acc[i][3], o1.z, o1.w);
            float* orow = o + (size_t)n * NFEAT;
            *reinterpret_cast<float4*>(orow + tx * 4)      = o0;
            *reinterpret_cast<float4*>(orow + tx * 4 + 32) = o1;
        }
    }
}

// ---------------------------------------------------------------------------
// Launch
// ---------------------------------------------------------------------------
extern "C" void kernel_launch(void* const* d_in, const int* in_sizes, int n_in,
                              void* d_out, int out_size)
{
    const int*   u_s    = (const int*)  d_in[0];
    const int*   v_s    = (const int*)  d_in[1];
    const int*   rate   = (const int*)  d_in[2];
    const float* x_user = (const float*)d_in[3];
    const float* x_item = (const float*)d_in[4];
    const float* weight = (const float*)d_in[5];
    float* out = (float*)d_out;

    int E = in_sizes[0];

    zero_cur_kernel<<<(NSEG / 4 + 255) / 256, 256>>>();

    fill_kernel<<<(E + 255) / 256, 256>>>(u_s, v_s, rate, E);

    segment_mean_kernel<<<(NSEG + 7) / 8, 256>>>(x_user, x_item);

    transform_fused_kernel<<<UBLOCKS + VBLOCKS, 256>>>(weight, out);
}

// round 10
// speedup vs baseline: 1.1509x; 1.0120x over previous
#include <cuda_runtime.h>
#include <cuda_bf16.h>
#include <cstdint>

// Problem constants (fixed shapes per reference)
#define NUM_EDGES 1000000
#define NUM_USERS 50000
#define NUM_ITEMS 20000
#define NRATE 5
#define NFEAT 64
#define KDIM (NRATE * NFEAT)   // 320

constexpr int NSEG_U = NUM_USERS * NRATE;   // 250,000
constexpr int NSEG_V = NUM_ITEMS * NRATE;   // 100,000
constexpr int NSEG   = NSEG_U + NSEG_V;     // 350,000

// Bucket capacities: counts ~Poisson(4) (u) / ~Poisson(10) (v); overflow
// probability ~1e-9 and writes clamp to cap so it can't corrupt memory.
constexpr int CAP_U = 32;
constexpr int CAP_V = 64;

// ---------------------------------------------------------------------------
// Static device scratch.  The mean matrix is stored as PACKED bf16 hi/lo
// k-pairs (u32 = {bf16(k+1)<<16 | bf16(k)}), which is exactly the mma.sync
// A-fragment register format.  Row = node, 160 u32 per row (K=320).
//   hi_u: u32[ 50000*160 ]   lo_u: same
//   hi_v: u32[ 20000*160 ]   lo_v: same
// All carved from g_scratch (22.4M u32 total).
// ---------------------------------------------------------------------------
constexpr size_t HI_U = 0;
constexpr size_t HI_V = (size_t)NUM_USERS * 160;                  //  8,000,000
constexpr size_t LO_U = HI_V + (size_t)NUM_ITEMS * 160;           // 11,200,000
constexpr size_t LO_V = LO_U + (size_t)NUM_USERS * 160;           // 19,200,000
constexpr size_t SCRATCH_TOTAL = LO_V + (size_t)NUM_ITEMS * 160;  // 22,400,000

__device__ __align__(16) uint32_t g_scratch[SCRATCH_TOTAL];
__device__ __align__(16) int      g_cur[NSEG];
__device__ __align__(16) int      g_slots_u[(size_t)NSEG_U * CAP_U];
__device__ __align__(16) int      g_slots_v[(size_t)NSEG_V * CAP_V];

// W pre-packed into B-fragment layout: [ks(20)][breg(2)][lane(32)][nblk(8)] u32
__device__ __align__(16) uint32_t g_WF_hi[20 * 2 * 32 * 8];   // 40KB
__device__ __align__(16) uint32_t g_WF_lo[20 * 2 * 32 * 8];   // 40KB

// ---------------------------------------------------------------------------
// helpers
// ---------------------------------------------------------------------------
__device__ __forceinline__ uint32_t pack_bf16(__nv_bfloat16 lo, __nv_bfloat16 hi) {
    return (uint32_t)__bfloat16_as_ushort(lo) | ((uint32_t)__bfloat16_as_ushort(hi) << 16);
}

__device__ __forceinline__ void mma16816(float* d, const uint32_t* a,
                                         uint32_t b0, uint32_t b1) {
    asm volatile(
        "mma.sync.aligned.m16n8k16.row.col.f32.bf16.bf16.f32 "
        "{%0,%1,%2,%3},{%4,%5,%6,%7},{%8,%9},{%0,%1,%2,%3};"
        : "+f"(d[0]), "+f"(d[1]), "+f"(d[2]), "+f"(d[3])
        : "r"(a[0]), "r"(a[1]), "r"(a[2]), "r"(a[3]), "r"(b0), "r"(b1));
}

// ---------------------------------------------------------------------------
// Kernel 0: pack W into B-fragment layout (hi/lo bf16 split).
// Entry [ks][b][l][j] = {W[k][n], W[k+1][n]} with n = 8j + l/4,
// k = ks*16 + b*8 + (l%4)*2.   20 blocks, one per ks.
// ---------------------------------------------------------------------------
__global__ void __launch_bounds__(256) wformat_kernel(const float* __restrict__ W) {
    int ks = blockIdx.x;
    for (int idx = threadIdx.x; idx < 512; idx += 256) {
        int bb = idx >> 8;
        int rem = idx & 255;
        int l = rem >> 3;
        int j = rem & 7;
        int n = 8 * j + (l >> 2);
        int k = ks * 16 + bb * 8 + (l & 3) * 2;
        float f0 = __ldg(W + (size_t)k * NFEAT + n);
        float f1 = __ldg(W + (size_t)(k + 1) * NFEAT + n);
        __nv_bfloat16 h0 = __float2bfloat16(f0);
        __nv_bfloat16 h1 = __float2bfloat16(f1);
        float r0 = f0 - __bfloat162float(h0);
        float r1 = f1 - __bfloat162float(h1);
        int o = ((ks * 2 + bb) * 32 + l) * 8 + j;
        g_WF_hi[o] = pack_bf16(h0, h1);
        g_WF_lo[o] = pack_bf16(__float2bfloat16(r0), __float2bfloat16(r1));
    }
}

// ---------------------------------------------------------------------------
// Kernel 1: zero the cursors
// ---------------------------------------------------------------------------
__global__ void __launch_bounds__(256) zero_cur_kernel() {
    int i = blockIdx.x * blockDim.x + threadIdx.x;
    if (i < NSEG / 4) reinterpret_cast<int4*>(g_cur)[i] = make_int4(0, 0, 0, 0);
}

// ---------------------------------------------------------------------------
// Kernel 2: bucket fill (cursor atomicAdd doubles as histogram)
// ---------------------------------------------------------------------------
__global__ void __launch_bounds__(256) fill_kernel(
    const int* __restrict__ u_s,
    const int* __restrict__ v_s,
    const int* __restrict__ rate,
    int E)
{
    int e = blockIdx.x * blockDim.x + threadIdx.x;
    if (e >= E) return;

    int u = __ldg(u_s + e);
    int v = __ldg(v_s + e);
    int r = __ldg(rate + e);

    int segu = u * NRATE + r;
    int pos  = atomicAdd(g_cur + segu, 1);
    if (pos < CAP_U) g_slots_u[(size_t)segu * CAP_U + pos] = v;

    int segv = v * NRATE + r;
    int pos2 = atomicAdd(g_cur + NSEG_U + segv, 1);
    if (pos2 < CAP_V) g_slots_v[(size_t)segv * CAP_V + pos2] = u;
}

// ---------------------------------------------------------------------------
// Kernel 3: segmented mean -> packed bf16 hi/lo.  One warp per segment,
// two source rows per iteration (16-lane halves), shfl_xor(16) combine.
// Segment gw's 64 mean values live at u32 offset gw*32 in its region
// (node*320 + r*64 == gw*64 floats == gw*32 u32 k-pairs).
// ---------------------------------------------------------------------------
__global__ void __launch_bounds__(256) segment_mean_kernel(
    const float* __restrict__ x_user,
    const float* __restrict__ x_item)
{
    int gw   = (blockIdx.x * blockDim.x + threadIdx.x) >> 5;
    int lane = threadIdx.x & 31;
    if (gw >= NSEG) return;

    const float* __restrict__ x;
    const int*   __restrict__ slots;
    uint32_t *hi, *lo;
    int cap;
    if (gw < NSEG_U) {
        x     = x_item;
        slots = g_slots_u + (size_t)gw * CAP_U;
        hi    = g_scratch + HI_U + (size_t)gw * 32;
        lo    = g_scratch + LO_U + (size_t)gw * 32;
        cap   = CAP_U;
    } else {
        int s = gw - NSEG_U;
        x     = x_user;
        slots = g_slots_v + (size_t)s * CAP_V;
        hi    = g_scratch + HI_V + (size_t)s * 32;
        lo    = g_scratch + LO_V + (size_t)s * 32;
        cap   = CAP_V;
    }

    int cnt = __ldg(g_cur + gw);
    int cc  = min(cnt, cap);

    int half = lane >> 4;
    int fl   = lane & 15;

    int my = (lane < min(cc, 32)) ? __ldg(slots + lane) : 0;

    float4 acc = make_float4(0.f, 0.f, 0.f, 0.f);

    int cmain = min(cc, 32);
    int npair = (cmain + 1) >> 1;
    #pragma unroll 4
    for (int p = 0; p < npair; ++p) {
        int e = 2 * p + half;
        int src = __shfl_sync(0xffffffffu, my, e & 31);
        if (e < cmain) {
            float4 f = *reinterpret_cast<const float4*>(x + (size_t)src * NFEAT + fl * 4);
            acc.x += f.x; acc.y += f.y; acc.z += f.z; acc.w += f.w;
        }
    }
    for (int e = 32 + half; e < cc; e += 2) {
        int src = __ldg(slots + e);
        float4 f = *reinterpret_cast<const float4*>(x + (size_t)src * NFEAT + fl * 4);
        acc.x += f.x; acc.y += f.y; acc.z += f.z; acc.w += f.w;
    }

    acc.x += __shfl_xor_sync(0xffffffffu, acc.x, 16);
    acc.y += __shfl_xor_sync(0xffffffffu, acc.y, 16);
    acc.z += __shfl_xor_sync(0xffffffffu, acc.z, 16);
    acc.w += __shfl_xor_sync(0xffffffffu, acc.w, 16);

    if (lane < 16) {
        float inv = 1.0f / (float)max(cnt, 1);
        float m0 = acc.x * inv, m1 = acc.y * inv, m2 = acc.z * inv, m3 = acc.w * inv;
        __nv_bfloat16 h0 = __float2bfloat16(m0), h1 = __float2bfloat16(m1);
        __nv_bfloat16 h2 = __float2bfloat16(m2), h3 = __float2bfloat16(m3);
        uint2 hv, lv;
        hv.x = pack_bf16(h0, h1);
        hv.y = pack_bf16(h2, h3);
        lv.x = pack_bf16(__float2bfloat16(m0 - __bfloat162float(h0)),
                         __float2bfloat16(m1 - __bfloat162float(h1)));
        lv.y = pack_bf16(__float2bfloat16(m2 - __bfloat162float(h2)),
                         __float2bfloat16(m3 - __bfloat162float(h3)));
        reinterpret_cast<uint2*>(hi)[fl] = hv;   // k-pairs fl*2, fl*2+1
        reinterpret_cast<uint2*>(lo)[fl] = lv;
    }
}

// ---------------------------------------------------------------------------
// Kernel 4: tensor-core transform via mma.sync (HMMA, base-target safe).
//   out[n,h] = sum_k mean[n,k] * W[k,h],  bf16 two-term split, 3 MMAs/step.
// Grid: 548 blocks x 256 threads; each warp owns a 16-row x 64-col tile.
// No shared memory, no block syncs: A frags via LDG.32 from packed means,
// B frags via LDG.128 from the 80KB pre-formatted W (L1-resident).
// Per warp: 20 k-steps x (8 LDG.32 + 8 LDG.128 + 24 HMMA.16816).
// ---------------------------------------------------------------------------
constexpr int TILE_M = 128;                                  // rows per block
constexpr int UTB = (NUM_USERS + TILE_M - 1) / TILE_M;       // 391
constexpr int VTB = (NUM_ITEMS + TILE_M - 1) / TILE_M;       // 157

__global__ void __launch_bounds__(256) transform_mma_kernel(float* __restrict__ out)
{
    int b = blockIdx.x;
    const uint32_t *mh, *ml;
    int n_nodes, base;
    float* o;
    if (b < UTB) {
        mh = g_scratch + HI_U; ml = g_scratch + LO_U;
        n_nodes = NUM_USERS; base = b * TILE_M; o = out;
    } else {
        mh = g_scratch + HI_V; ml = g_scratch + LO_V;
        n_nodes = NUM_ITEMS; base = (b - UTB) * TILE_M;
        o = out + (size_t)NUM_USERS * NFEAT;
    }

    int t   = threadIdx.x;
    int wid = t >> 5;
    int l   = t & 31;

    int m0 = base + wid * 16;
    int r0 = m0 + (l >> 2);
    int r1 = r0 + 8;
    int r0c = min(r0, n_nodes - 1);
    int r1c = min(r1, n_nodes - 1);

    const uint32_t* A0h = mh + (size_t)r0c * 160 + (l & 3);
    const uint32_t* A1h = mh + (size_t)r1c * 160 + (l & 3);
    const uint32_t* A0l = ml + (size_t)r0c * 160 + (l & 3);
    const uint32_t* A1l = ml + (size_t)r1c * 160 + (l & 3);

    float acc[8][4];
    #pragma unroll
    for (int j = 0; j < 8; ++j)
        #pragma unroll
        for (int i = 0; i < 4; ++i) acc[j][i] = 0.f;

    #pragma unroll 2
    for (int ks = 0; ks < 20; ++ks) {
        int ko = ks * 8;
        uint32_t ah[4], al[4];
        ah[0] = __ldg(A0h + ko);     ah[1] = __ldg(A1h + ko);
        ah[2] = __ldg(A0h + ko + 4); ah[3] = __ldg(A1h + ko + 4);
        al[0] = __ldg(A0l + ko);     al[1] = __ldg(A1l + ko);
        al[2] = __ldg(A0l + ko + 4); al[3] = __ldg(A1l + ko + 4);

        const uint4* bh0p = reinterpret_cast<const uint4*>(g_WF_hi) + ((ks * 2 + 0) * 32 + l) * 2;
        const uint4* bh1p = reinterpret_cast<const uint4*>(g_WF_hi) + ((ks * 2 + 1) * 32 + l) * 2;
        const uint4* bl0p = reinterpret_cast<const uint4*>(g_WF_lo) + ((ks * 2 + 0) * 32 + l) * 2;
        const uint4* bl1p = reinterpret_cast<const uint4*>(g_WF_lo) + ((ks * 2 + 1) * 32 + l) * 2;
        uint4 bh0a = __ldg(bh0p), bh0b = __ldg(bh0p + 1);
        uint4 bh1a = __ldg(bh1p), bh1b = __ldg(bh1p + 1);
        uint4 bl0a = __ldg(bl0p), bl0b = __ldg(bl0p + 1);
        uint4 bl1a = __ldg(bl1p), bl1b = __ldg(bl1p + 1);

        uint32_t b0h[8] = {bh0a.x, bh0a.y, bh0a.z, bh0a.w, bh0b.x, bh0b.y, bh0b.z, bh0b.w};
        uint32_t b1h[8] = {bh1a.x, bh1a.y, bh1a.z, bh1a.w, bh1b.x, bh1b.y, bh1b.z, bh1b.w};
        uint32_t b0l[8] = {bl0a.x, bl0a.y, bl0a.z, bl0a.w, bl0b.x, bl0b.y, bl0b.z, bl0b.w};
        uint32_t b1l[8] = {bl1a.x, bl1a.y, bl1a.z, bl1a.w, bl1b.x, bl1b.y, bl1b.z, bl1b.w};

        #pragma unroll
        for (int j = 0; j < 8; ++j) {
            mma16816(acc[j], ah, b0h[j], b1h[j]);   // hi*hi
            mma16816(acc[j], ah, b0l[j], b1l[j]);   // hi*lo
            mma16816(acc[j], al, b0h[j], b1h[j]);   // lo*hi
        }
    }

    // ---- epilogue: lane l holds cols (l%4)*2,+1 of rows r0 and r1 per nblk ----
    float* orow0 = o + (size_t)r0 * NFEAT;
    float* orow1 = o + (size_t)r1 * NFEAT;
    bool v0 = (r0 < n_nodes), v1 = (r1 < n_nodes);
    #pragma unroll
    for (int j = 0; j < 8; ++j) {
        int n = j * 8 + (l & 3) * 2;
        if (v0) *reinterpret_cast<float2*>(orow0 + n) = make_float2(acc[j][0], acc[j][1]);
        if (v1) *reinterpret_cast<float2*>(orow1 + n) = make_float2(acc[j][2], acc[j][3]);
    }
}

// ---------------------------------------------------------------------------
// Launch
// ---------------------------------------------------------------------------
extern "C" void kernel_launch(void* const* d_in, const int* in_sizes, int n_in,
                              void* d_out, int out_size)
{
    const int*   u_s    = (const int*)  d_in[0];
    const int*   v_s    = (const int*)  d_in[1];
    const int*   rate   = (const int*)  d_in[2];
    const float* x_user = (const float*)d_in[3];
    const float* x_item = (const float*)d_in[4];
    const float* weight = (const float*)d_in[5];
    float* out = (float*)d_out;

    int E = in_sizes[0];

    wformat_kernel<<<20, 256>>>(weight);

    zero_cur_kernel<<<(NSEG / 4 + 255) / 256, 256>>>();

    fill_kernel<<<(E + 255) / 256, 256>>>(u_s, v_s, rate, E);

    segment_mean_kernel<<<(NSEG + 7) / 8, 256>>>(x_user, x_item);

    transform_mma_kernel<<<UTB + VTB, 256>>>(out);
}

// round 11
// speedup vs baseline: 1.3421x; 1.1661x over previous
#include <cuda_runtime.h>
#include <cuda_bf16.h>
#include <cstdint>

// Problem constants (fixed shapes per reference)
#define NUM_EDGES 1000000
#define NUM_USERS 50000
#define NUM_ITEMS 20000
#define NRATE 5
#define NFEAT 64
#define KDIM (NRATE * NFEAT)   // 320

// ---------------------------------------------------------------------------
// Static device scratch (allocation is forbidden)
//   sums: sum_u [50000][5][64] ++ sum_v [20000][5][64]   (fp32)
//   cnts: cnt_u [50000][5] ++ cnt_v [20000][5]           (fp32)
// ---------------------------------------------------------------------------
constexpr size_t SUM_U_OFF = 0;
constexpr size_t SUM_V_OFF = (size_t)NUM_USERS * KDIM;                 // 16,000,000
constexpr size_t SUMS_TOTAL = SUM_V_OFF + (size_t)NUM_ITEMS * KDIM;    // 22,400,000
constexpr size_t CNT_U_OFF = SUMS_TOTAL;                               // 22,400,000
constexpr size_t CNT_V_OFF = CNT_U_OFF + (size_t)NUM_USERS * NRATE;    // 22,650,000
constexpr size_t SCRATCH_TOTAL = CNT_V_OFF + (size_t)NUM_ITEMS * NRATE;// 22,750,000 floats

__device__ __align__(16) float g_scratch[SCRATCH_TOTAL];

// W pre-packed into mma.sync B-fragment layout:
//   [ks(20)][breg(2)][lane(32)][nblk(8)] u32, bf16 hi/lo split (40KB each)
__device__ __align__(16) uint32_t g_WF_hi[20 * 2 * 32 * 8];
__device__ __align__(16) uint32_t g_WF_lo[20 * 2 * 32 * 8];

// ---------------------------------------------------------------------------
// helpers
// ---------------------------------------------------------------------------
__device__ __forceinline__ void red_add_v4(float* p, float4 v) {
    unsigned long long gp = (unsigned long long)__cvta_generic_to_global(p);
    asm volatile("red.global.add.v4.f32 [%0], {%1, %2, %3, %4};"
                 :: "l"(gp), "f"(v.x), "f"(v.y), "f"(v.z), "f"(v.w)
                 : "memory");
}
__device__ __forceinline__ uint32_t pack_bf16(__nv_bfloat16 lo, __nv_bfloat16 hi) {
    return (uint32_t)__bfloat16_as_ushort(lo) | ((uint32_t)__bfloat16_as_ushort(hi) << 16);
}
// split x into bf16 hi + bf16 lo residual
__device__ __forceinline__ void bf16_split(float x, __nv_bfloat16& h, __nv_bfloat16& l) {
    h = __float2bfloat16(x);
    l = __float2bfloat16(x - __bfloat162float(h));
}
__device__ __forceinline__ void mma16816(float* d, const uint32_t* a,
                                         uint32_t b0, uint32_t b1) {
    asm volatile(
        "mma.sync.aligned.m16n8k16.row.col.f32.bf16.bf16.f32 "
        "{%0,%1,%2,%3},{%4,%5,%6,%7},{%8,%9},{%0,%1,%2,%3};"
        : "+f"(d[0]), "+f"(d[1]), "+f"(d[2]), "+f"(d[3])
        : "r"(a[0]), "r"(a[1]), "r"(a[2]), "r"(a[3]), "r"(b0), "r"(b1));
}

// ---------------------------------------------------------------------------
// Kernel 0: pack W into B-fragment layout (hi/lo bf16 split).
// Entry [ks][b][l][j] = {W[k][n], W[k+1][n]} with n = 8j + l/4,
// k = ks*16 + b*8 + (l%4)*2.   20 blocks, one per ks.
// ---------------------------------------------------------------------------
__global__ void __launch_bounds__(256) wformat_kernel(const float* __restrict__ W) {
    int ks = blockIdx.x;
    for (int idx = threadIdx.x; idx < 512; idx += 256) {
        int bb = idx >> 8;
        int rem = idx & 255;
        int l = rem >> 3;
        int j = rem & 7;
        int n = 8 * j + (l >> 2);
        int k = ks * 16 + bb * 8 + (l & 3) * 2;
        float f0 = __ldg(W + (size_t)k * NFEAT + n);
        float f1 = __ldg(W + (size_t)(k + 1) * NFEAT + n);
        __nv_bfloat16 h0, l0, h1, l1;
        bf16_split(f0, h0, l0);
        bf16_split(f1, h1, l1);
        int o = ((ks * 2 + bb) * 32 + l) * 8 + j;
        g_WF_hi[o] = pack_bf16(h0, h1);
        g_WF_lo[o] = pack_bf16(l0, l1);
    }
}

// ---------------------------------------------------------------------------
// Kernel 1: zero sums + counts (91MB, float4 stores)
// ---------------------------------------------------------------------------
__global__ void __launch_bounds__(256) zero_kernel() {
    size_t i = (size_t)blockIdx.x * blockDim.x + threadIdx.x;
    float4* p = reinterpret_cast<float4*>(g_scratch);
    if (i < (SCRATCH_TOTAL + 3) / 4) p[i] = make_float4(0.f, 0.f, 0.f, 0.f);
}

// ---------------------------------------------------------------------------
// Kernel 2: edge scatter (R4's measured-63us design).
// Half-warp per edge: coalesced 256B feature gather, one red.global.add.v4
// per direction, lane 0 bumps the two (dst,rating) counts.
// ---------------------------------------------------------------------------
__global__ void __launch_bounds__(256) scatter_kernel(
    const int*   __restrict__ u_s,
    const int*   __restrict__ v_s,
    const int*   __restrict__ rate,
    const float* __restrict__ x_user,
    const float* __restrict__ x_item,
    int E)
{
    int gw   = (blockIdx.x * blockDim.x + threadIdx.x) >> 5;
    int lane = threadIdx.x & 31;
    int hl   = lane & 15;
    int sub  = lane >> 4;
    int base = gw * 8;

    #pragma unroll
    for (int it = 0; it < 4; ++it) {
        int e = base + it * 2 + sub;
        if (e >= E) break;  // e is monotone in it -> per-thread break is safe

        int u = __ldg(u_s + e);
        int v = __ldg(v_s + e);
        int r = __ldg(rate + e);

        float4 xi = reinterpret_cast<const float4*>(x_item + (size_t)v * NFEAT)[hl];
        red_add_v4(g_scratch + SUM_U_OFF + ((size_t)u * NRATE + r) * NFEAT + hl * 4, xi);

        float4 xu = reinterpret_cast<const float4*>(x_user + (size_t)u * NFEAT)[hl];
        red_add_v4(g_scratch + SUM_V_OFF + ((size_t)v * NRATE + r) * NFEAT + hl * 4, xu);

        if (hl == 0) {
            atomicAdd(g_scratch + CNT_U_OFF + (size_t)u * NRATE + r, 1.0f);
            atomicAdd(g_scratch + CNT_V_OFF + (size_t)v * NRATE + r, 1.0f);
        }
    }
}

// ---------------------------------------------------------------------------
// Kernel 3: tensor-core transform via mma.sync (base-target-safe HMMA).
//   out[n,h] = sum_k (sum[n,k]/max(cnt[n,k/64],1)) * W[k,h]
// bf16 two-term split (hi*hi + hi*lo + lo*hi), 3 MMAs per K16 step.
// 548 blocks x 256 threads; each warp owns a 16-row x 64-col tile with no
// shared memory and no block syncs. A fragments are built in registers from
// fp32 sums (LDG.64 pairs) with the per-rating reciprocal applied inline.
// ---------------------------------------------------------------------------
constexpr int TILE_M = 128;
constexpr int UTB = (NUM_USERS + TILE_M - 1) / TILE_M;       // 391
constexpr int VTB = (NUM_ITEMS + TILE_M - 1) / TILE_M;       // 157

__global__ void __launch_bounds__(256) transform_mma_kernel(float* __restrict__ out)
{
    int b = blockIdx.x;
    const float* sums;
    const float* cnts;
    int n_nodes, base;
    float* o;
    if (b < UTB) {
        sums = g_scratch + SUM_U_OFF; cnts = g_scratch + CNT_U_OFF;
        n_nodes = NUM_USERS; base = b * TILE_M; o = out;
    } else {
        sums = g_scratch + SUM_V_OFF; cnts = g_scratch + CNT_V_OFF;
        n_nodes = NUM_ITEMS; base = (b - UTB) * TILE_M;
        o = out + (size_t)NUM_USERS * NFEAT;
    }

    int t   = threadIdx.x;
    int wid = t >> 5;
    int l   = t & 31;

    int r0 = base + wid * 16 + (l >> 2);
    int r1 = r0 + 8;
    int r0c = min(r0, n_nodes - 1);
    int r1c = min(r1, n_nodes - 1);

    // per-rating reciprocals for this lane's two rows
    float inv0[NRATE], inv1[NRATE];
    #pragma unroll
    for (int rr = 0; rr < NRATE; ++rr) {
        inv0[rr] = 1.0f / fmaxf(__ldg(cnts + (size_t)r0c * NRATE + rr), 1.0f);
        inv1[rr] = 1.0f / fmaxf(__ldg(cnts + (size_t)r1c * NRATE + rr), 1.0f);
    }

    const float* S0 = sums + (size_t)r0c * KDIM + (l & 3) * 2;
    const float* S1 = sums + (size_t)r1c * KDIM + (l & 3) * 2;

    float acc[8][4];
    #pragma unroll
    for (int j = 0; j < 8; ++j)
        #pragma unroll
        for (int i = 0; i < 4; ++i) acc[j][i] = 0.f;

    #pragma unroll 4
    for (int ks = 0; ks < 20; ++ks) {
        int rr = ks >> 2;              // rating for this K16 step
        int ko = ks * 16;

        // A fragment: row r0 k-pair and k+8 pair; row r1 likewise
        float2 p00 = *reinterpret_cast<const float2*>(S0 + ko);
        float2 p10 = *reinterpret_cast<const float2*>(S1 + ko);
        float2 p02 = *reinterpret_cast<const float2*>(S0 + ko + 8);
        float2 p12 = *reinterpret_cast<const float2*>(S1 + ko + 8);

        float m00 = p00.x * inv0[rr], m01 = p00.y * inv0[rr];
        float m10 = p10.x * inv1[rr], m11 = p10.y * inv1[rr];
        float m02 = p02.x * inv0[rr], m03 = p02.y * inv0[rr];
        float m12 = p12.x * inv1[rr], m13 = p12.y * inv1[rr];

        __nv_bfloat16 h, lo;
        uint32_t ah[4], al[4];
        __nv_bfloat16 h2, lo2;
        bf16_split(m00, h, lo); bf16_split(m01, h2, lo2);
        ah[0] = pack_bf16(h, h2); al[0] = pack_bf16(lo, lo2);
        bf16_split(m10, h, lo); bf16_split(m11, h2, lo2);
        ah[1] = pack_bf16(h, h2); al[1] = pack_bf16(lo, lo2);
        bf16_split(m02, h, lo); bf16_split(m03, h2, lo2);
        ah[2] = pack_bf16(h, h2); al[2] = pack_bf16(lo, lo2);
        bf16_split(m12, h, lo); bf16_split(m13, h2, lo2);
        ah[3] = pack_bf16(h, h2); al[3] = pack_bf16(lo, lo2);

        // B fragments (pre-formatted, L1-resident 80KB)
        const uint4* bh0p = reinterpret_cast<const uint4*>(g_WF_hi) + ((ks * 2 + 0) * 32 + l) * 2;
        const uint4* bh1p = reinterpret_cast<const uint4*>(g_WF_hi) + ((ks * 2 + 1) * 32 + l) * 2;
        const uint4* bl0p = reinterpret_cast<const uint4*>(g_WF_lo) + ((ks * 2 + 0) * 32 + l) * 2;
        const uint4* bl1p = reinterpret_cast<const uint4*>(g_WF_lo) + ((ks * 2 + 1) * 32 + l) * 2;
        uint4 bh0a = __ldg(bh0p), bh0b = __ldg(bh0p + 1);
        uint4 bh1a = __ldg(bh1p), bh1b = __ldg(bh1p + 1);
        uint4 bl0a = __ldg(bl0p), bl0b = __ldg(bl0p + 1);
        uint4 bl1a = __ldg(bl1p), bl1b = __ldg(bl1p + 1);

        uint32_t b0h[8] = {bh0a.x, bh0a.y, bh0a.z, bh0a.w, bh0b.x, bh0b.y, bh0b.z, bh0b.w};
        uint32_t b1h[8] = {bh1a.x, bh1a.y, bh1a.z, bh1a.w, bh1b.x, bh1b.y, bh1b.z, bh1b.w};
        uint32_t b0l[8] = {bl0a.x, bl0a.y, bl0a.z, bl0a.w, bl0b.x, bl0b.y, bl0b.z, bl0b.w};
        uint32_t b1l[8] = {bl1a.x, bl1a.y, bl1a.z, bl1a.w, bl1b.x, bl1b.y, bl1b.z, bl1b.w};

        #pragma unroll
        for (int j = 0; j < 8; ++j) {
            mma16816(acc[j], ah, b0h[j], b1h[j]);   // hi*hi
            mma16816(acc[j], ah, b0l[j], b1l[j]);   // hi*lo
            mma16816(acc[j], al, b0h[j], b1h[j]);   // lo*hi
        }
    }

    // ---- epilogue: lane l holds cols (l%4)*2,+1 of rows r0,r1 per nblk ----
    float* orow0 = o + (size_t)r0 * NFEAT;
    float* orow1 = o + (size_t)r1 * NFEAT;
    bool v0 = (r0 < n_nodes), v1 = (r1 < n_nodes);
    #pragma unroll
    for (int j = 0; j < 8; ++j) {
        int n = j * 8 + (l & 3) * 2;
        if (v0) *reinterpret_cast<float2*>(orow0 + n) = make_float2(acc[j][0], acc[j][1]);
        if (v1) *reinterpret_cast<float2*>(orow1 + n) = make_float2(acc[j][2], acc[j][3]);
    }
}

// ---------------------------------------------------------------------------
// Launch
// ---------------------------------------------------------------------------
extern "C" void kernel_launch(void* const* d_in, const int* in_sizes, int n_in,
                              void* d_out, int out_size)
{
    const int*   u_s    = (const int*)  d_in[0];
    const int*   v_s    = (const int*)  d_in[1];
    const int*   rate   = (const int*)  d_in[2];
    const float* x_user = (const float*)d_in[3];
    const float* x_item = (const float*)d_in[4];
    const float* weight = (const float*)d_in[5];
    float* out = (float*)d_out;

    int E = in_sizes[0];

    wformat_kernel<<<20, 256>>>(weight);

    int zblocks = (int)(((SCRATCH_TOTAL + 3) / 4 + 255) / 256);
    zero_kernel<<<zblocks, 256>>>();

    int sblocks = (E + 63) / 64;   // 64 edges per 256-thread block
    scatter_kernel<<<sblocks, 256>>>(u_s, v_s, rate, x_user, x_item, E);

    transform_mma_kernel<<<UTB + VTB, 256>>>(out);
}